// round 3
// baseline (speedup 1.0000x reference)
#include <cuda_runtime.h>
#include <cuda_bf16.h>
#include <cstdint>

constexpr int Bn = 8, Cn = 128, Tn = 32768, Ln = 256;
constexpr float SLOPE = 0.2f;

// ---- device scratch ----
__device__ __nv_bfloat16 gA_hi[(size_t)Bn * Ln * 3 * Cn * Cn];  // [b][l][k][co][ci]
__device__ __nv_bfloat16 gA_lo[(size_t)Bn * Ln * 3 * Cn * Cn];
__device__ float         g_h  [(size_t)Bn * Cn * Tn];
__device__ __nv_bfloat16 gA2_hi[3 * Cn * Cn];                   // [k][co][ci]
__device__ __nv_bfloat16 gA2_lo[3 * Cn * Cn];

// ---- helpers ----
static __device__ __forceinline__ uint32_t smem_u32(const void* p) {
    uint32_t a;
    asm("{ .reg .u64 t; cvta.to.shared.u64 t, %1; cvt.u32.u64 %0, t; }" : "=r"(a) : "l"(p));
    return a;
}
static __device__ __forceinline__ void ldm_x4(uint32_t &r0, uint32_t &r1,
                                              uint32_t &r2, uint32_t &r3, uint32_t addr) {
    asm volatile("ldmatrix.sync.aligned.m8n8.x4.shared.b16 {%0,%1,%2,%3}, [%4];"
                 : "=r"(r0), "=r"(r1), "=r"(r2), "=r"(r3) : "r"(addr));
}
static __device__ __forceinline__ void mma16816(float* c, const uint32_t* a, const uint32_t* b) {
    asm volatile("mma.sync.aligned.m16n8k16.row.col.f32.bf16.bf16.f32 "
                 "{%0,%1,%2,%3}, {%4,%5,%6,%7}, {%8,%9}, {%0,%1,%2,%3};"
                 : "+f"(c[0]), "+f"(c[1]), "+f"(c[2]), "+f"(c[3])
                 : "r"(a[0]), "r"(a[1]), "r"(a[2]), "r"(a[3]), "r"(b[0]), "r"(b[1]));
}

// smem layout (bytes):
//  A buf0: [0, 69632)   = A_hi(128x136 bf16 = 34816) + A_lo(34816)
//  A buf1: [69632, 139264)
//  xT_hi : [139264, +36448)   rows: c (<=134), 136 bf16/row (272B stride)
//  xT_lo : [175712, +36448)   end = 212160
//  fp32 window reuses [0, 69120)  (dead before A staging starts)
constexpr uint32_t ABUF_SZ = 69632u;
constexpr uint32_t AHALF   = 34816u;
constexpr uint32_t XT_HI   = 139264u;
constexpr uint32_t XT_LO   = XT_HI + 36448u;
constexpr uint32_t SMEM_SZ = XT_LO + 36448u;   // 212160
constexpr int WSTR = 135;   // fp32 staging stride (odd -> conflict-free transpose reads)

// ---- prep kernels (same layouts as before) ----
__global__ void wn_prep_kernel(const float* __restrict__ conv_v,
                               const float* __restrict__ conv_g) {
    __shared__ float sc[Cn];
    int co = threadIdx.x;
    float s = 0.f;
    for (int i = 0; i < Cn * 3; ++i) {
        float t = conv_v[co * (Cn * 3) + i];
        s += t * t;
    }
    sc[co] = conv_g[co] / sqrtf(s);
    __syncthreads();
    for (int i = threadIdx.x; i < 3 * Cn * Cn; i += Cn) {
        int k = i >> 14, rest = i & 16383, c2 = rest >> 7, ci = rest & 127;
        float v = conv_v[(c2 * Cn + ci) * 3 + k] * sc[c2];
        __nv_bfloat16 h = __float2bfloat16(v);
        gA2_hi[i] = h;
        gA2_lo[i] = __float2bfloat16(v - __bfloat162float(h));
    }
}

__global__ void transpose_w_kernel(const float* __restrict__ W) {
    __shared__ float tile[32][33];
    int z = blockIdx.z;
    int k = z % 3, co = (z / 3) & 127, b = z / (3 * Cn);
    int l0 = blockIdx.x * 32, ci0 = blockIdx.y * 32;
    #pragma unroll
    for (int j = 0; j < 4; ++j) {
        int ci = ci0 + threadIdx.y + j * 8;
        tile[threadIdx.y + j * 8][threadIdx.x] =
            W[((((size_t)b * Cn + ci) * Cn + co) * 3 + k) * Ln + l0 + threadIdx.x];
    }
    __syncthreads();
    #pragma unroll
    for (int j = 0; j < 4; ++j) {
        int l = l0 + threadIdx.y + j * 8;
        float v = tile[threadIdx.x][threadIdx.y + j * 8];
        __nv_bfloat16 h = __float2bfloat16(v);
        size_t o = ((((size_t)b * Ln + l) * 3 + k) * Cn + co) * Cn + ci0 + threadIdx.x;
        gA_hi[o] = h;
        gA_lo[o] = __float2bfloat16(v - __bfloat162float(h));
    }
}

// ---- main GEMM kernel (HMMA bf16 hi/lo 3-pass) ----
template <int PAD, int SHIFT, bool LVC>
__global__ __launch_bounds__(256, 1)
void gemm_hmma_kernel(const float* __restrict__ src,
                      const __nv_bfloat16* __restrict__ Ah,
                      const __nv_bfloat16* __restrict__ Al,
                      const float* __restrict__ biasp,
                      float* __restrict__ dst) {
    constexpr int CROWS = 128 + 2 * PAD;
    extern __shared__ char sm[];
    const uint32_t smb = smem_u32(sm);
    const int tid = threadIdx.x;
    const int b = blockIdx.x >> 8, tile = blockIdx.x & 255;

    // 1) stage fp32 window coalesced: ws[ci][c], c = t - (tile*128 - PAD)
    {
        float* ws = (float*)sm;
        const int tb = tile * 128 - PAD;
        const float* xb = src + (size_t)b * Cn * Tn;
        for (int i = tid; i < Cn * CROWS; i += 256) {
            int ci = i / CROWS, c = i - ci * CROWS;
            int t = tb + c;
            ws[ci * WSTR + c] = (t >= 0 && t < Tn) ? xb[(size_t)ci * Tn + t] : 0.f;
        }
    }
    __syncthreads();
    // 2) transpose + split into xT_hi/xT_lo [c][ci] (272B row stride)
    {
        const float* ws = (const float*)sm;
        __nv_bfloat16* xh = (__nv_bfloat16*)(sm + XT_HI);
        __nv_bfloat16* xl = (__nv_bfloat16*)(sm + XT_LO);
        for (int i = tid; i < Cn * CROWS; i += 256) {
            int c = i >> 7, ci = i & 127;
            float v = ws[ci * WSTR + c];
            __nv_bfloat16 h = __float2bfloat16(v);
            xh[c * 136 + ci] = h;
            xl[c * 136 + ci] = __float2bfloat16(v - __bfloat162float(h));
        }
    }
    __syncthreads();

    const size_t a_off = LVC ? (size_t)(b * Ln + tile) * 3 * 16384 : 0;

    // A staging helper (gmem [co][ci] -> smem rows of 272B)
    auto stageA = [&](int k, uint32_t buf) {
        const uint4* sH = (const uint4*)(Ah + a_off + (size_t)k * 16384);
        const uint4* sL = (const uint4*)(Al + a_off + (size_t)k * 16384);
        #pragma unroll
        for (int j = 0; j < 8; ++j) {
            int i = tid + j * 256;
            int co = i >> 4, c8 = (i & 15) << 3;
            uint32_t d = buf + (uint32_t)co * 272u + (uint32_t)c8 * 2u;
            *(uint4*)(sm + d) = sH[i];
            *(uint4*)(sm + d + AHALF) = sL[i];
        }
    };

    stageA(0, 0);

    // warp tiling: 8 warps -> (4 co-tiles of 32) x (2 s-tiles of 64)
    const int warp = tid >> 5, lane = tid & 31;
    const int co0 = (warp >> 1) * 32, s0 = (warp & 1) * 64;
    const uint32_t lrow = lane & 15, lcol = (lane >> 4) << 4;

    float acc[2][8][4];
    #pragma unroll
    for (int mi = 0; mi < 2; ++mi)
        #pragma unroll
        for (int ni = 0; ni < 8; ++ni)
            #pragma unroll
            for (int q = 0; q < 4; ++q) acc[mi][ni][q] = 0.f;

    // per-thread ldmatrix base offsets
    uint32_t aoff[2];
    #pragma unroll
    for (int mi = 0; mi < 2; ++mi)
        aoff[mi] = (uint32_t)(co0 + mi * 16 + lrow) * 272u + lcol;
    uint32_t boff[4];
    #pragma unroll
    for (int p = 0; p < 4; ++p)
        boff[p] = (uint32_t)(s0 + p * 16 + lrow) * 272u + lcol;

    #pragma unroll
    for (int k = 0; k < 3; ++k) {
        __syncthreads();
        const uint32_t buf = (k & 1) ? ABUF_SZ : 0u;
        if (k < 2) stageA(k + 1, (k & 1) ? 0u : ABUF_SZ);

        const uint32_t abase = smb + buf;
        const uint32_t bshift = (uint32_t)(SHIFT * k) * 272u;
        const uint32_t bh_base = smb + XT_HI + bshift;
        const uint32_t bl_base = smb + XT_LO + bshift;

        #pragma unroll 2
        for (int ch = 0; ch < 8; ++ch) {
            const uint32_t cb = (uint32_t)ch * 32u;   // ci0*2 bytes
            uint32_t ahf[2][4], alf[2][4];
            #pragma unroll
            for (int mi = 0; mi < 2; ++mi) {
                ldm_x4(ahf[mi][0], ahf[mi][1], ahf[mi][2], ahf[mi][3], abase + aoff[mi] + cb);
                ldm_x4(alf[mi][0], alf[mi][1], alf[mi][2], alf[mi][3], abase + AHALF + aoff[mi] + cb);
            }
            uint32_t bh[8][2], bl[8][2];
            #pragma unroll
            for (int p = 0; p < 4; ++p) {
                uint32_t r0, r1, r2, r3;
                ldm_x4(r0, r1, r2, r3, bh_base + boff[p] + cb);
                bh[2 * p][0] = r0; bh[2 * p][1] = r2;
                bh[2 * p + 1][0] = r1; bh[2 * p + 1][1] = r3;
                ldm_x4(r0, r1, r2, r3, bl_base + boff[p] + cb);
                bl[2 * p][0] = r0; bl[2 * p][1] = r2;
                bl[2 * p + 1][0] = r1; bl[2 * p + 1][1] = r3;
            }
            #pragma unroll
            for (int mi = 0; mi < 2; ++mi)
                #pragma unroll
                for (int ni = 0; ni < 8; ++ni) {
                    mma16816(acc[mi][ni], ahf[mi], bh[ni]);   // hi*hi
                    mma16816(acc[mi][ni], ahf[mi], bl[ni]);   // hi*lo
                    mma16816(acc[mi][ni], alf[mi], bh[ni]);   // lo*hi
                }
        }
    }

    // epilogue: bias + leaky, direct float2 stores (32B-sector aligned)
    const int g = lane >> 2, q = lane & 3;
    float bv[2][2];
    #pragma unroll
    for (int mi = 0; mi < 2; ++mi)
        #pragma unroll
        for (int h = 0; h < 2; ++h) {
            int co = co0 + mi * 16 + g + h * 8;
            bv[mi][h] = LVC ? biasp[((size_t)b * Cn + co) * Ln + tile] : biasp[co];
        }
    float* dbase = dst + (size_t)b * Cn * Tn + (size_t)tile * 128;
    #pragma unroll
    for (int mi = 0; mi < 2; ++mi)
        #pragma unroll
        for (int ni = 0; ni < 8; ++ni)
            #pragma unroll
            for (int h = 0; h < 2; ++h) {
                int co = co0 + mi * 16 + g + h * 8;
                int s = s0 + ni * 8 + q * 2;
                float v0 = acc[mi][ni][2 * h]     + bv[mi][h];
                float v1 = acc[mi][ni][2 * h + 1] + bv[mi][h];
                v0 = fmaxf(v0, SLOPE * v0);
                v1 = fmaxf(v1, SLOPE * v1);
                *(float2*)(dbase + (size_t)co * Tn + s) = make_float2(v0, v1);
            }
}

// ---- launch ----
extern "C" void kernel_launch(void* const* d_in, const int* in_sizes, int n_in,
                              void* d_out, int out_size) {
    const float* x      = (const float*)d_in[0];
    const float* weight = (const float*)d_in[1];
    const float* bias   = (const float*)d_in[2];
    const float* conv_v = (const float*)d_in[3];
    const float* conv_g = (const float*)d_in[4];
    const float* conv_b = (const float*)d_in[5];
    float* out = (float*)d_out;

    float* gh_ptr;
    cudaGetSymbolAddress((void**)&gh_ptr, g_h);
    __nv_bfloat16 *pAh, *pAl, *pA2h, *pA2l;
    cudaGetSymbolAddress((void**)&pAh, gA_hi);
    cudaGetSymbolAddress((void**)&pAl, gA_lo);
    cudaGetSymbolAddress((void**)&pA2h, gA2_hi);
    cudaGetSymbolAddress((void**)&pA2l, gA2_lo);

    cudaFuncSetAttribute(gemm_hmma_kernel<1, 1, true>,
                         cudaFuncAttributeMaxDynamicSharedMemorySize, SMEM_SZ);
    cudaFuncSetAttribute(gemm_hmma_kernel<3, 3, false>,
                         cudaFuncAttributeMaxDynamicSharedMemorySize, SMEM_SZ);

    wn_prep_kernel<<<1, Cn>>>(conv_v, conv_g);
    transpose_w_kernel<<<dim3(Ln / 32, Cn / 32, Bn * Cn * 3), dim3(32, 8)>>>(weight);
    gemm_hmma_kernel<1, 1, true><<<Bn * Ln, 256, SMEM_SZ>>>(x, pAh, pAl, bias, gh_ptr);
    gemm_hmma_kernel<3, 3, false><<<Bn * Ln, 256, SMEM_SZ>>>(gh_ptr, pA2h, pA2l, conv_b, out);
}

// round 4
// speedup vs baseline: 1.1863x; 1.1863x over previous
#include <cuda_runtime.h>
#include <cuda_bf16.h>
#include <cstdint>

constexpr int Bn = 8, Cn = 128, Tn = 32768, Ln = 256;
constexpr float SLOPE = 0.2f;

// ---- device scratch ----
__device__ __nv_bfloat16 gA_hi[(size_t)Bn * Ln * 3 * Cn * Cn];  // [b][l][k][co][ci]
__device__ __nv_bfloat16 gA_lo[(size_t)Bn * Ln * 3 * Cn * Cn];
__device__ float         g_h  [(size_t)Bn * Cn * Tn];
__device__ __nv_bfloat16 gA2_hi[3 * Cn * Cn];                   // [k][co][ci]
__device__ __nv_bfloat16 gA2_lo[3 * Cn * Cn];

// ---- helpers ----
static __device__ __forceinline__ uint32_t smem_u32(const void* p) {
    uint32_t a;
    asm("{ .reg .u64 t; cvta.to.shared.u64 t, %1; cvt.u32.u64 %0, t; }" : "=r"(a) : "l"(p));
    return a;
}
static __device__ __forceinline__ void ldm_x4(uint32_t &r0, uint32_t &r1,
                                              uint32_t &r2, uint32_t &r3, uint32_t addr) {
    asm volatile("ldmatrix.sync.aligned.m8n8.x4.shared.b16 {%0,%1,%2,%3}, [%4];"
                 : "=r"(r0), "=r"(r1), "=r"(r2), "=r"(r3) : "r"(addr));
}
static __device__ __forceinline__ void mma16816(float* c, const uint32_t* a, const uint32_t* b) {
    asm volatile("mma.sync.aligned.m16n8k16.row.col.f32.bf16.bf16.f32 "
                 "{%0,%1,%2,%3}, {%4,%5,%6,%7}, {%8,%9}, {%0,%1,%2,%3};"
                 : "+f"(c[0]), "+f"(c[1]), "+f"(c[2]), "+f"(c[3])
                 : "r"(a[0]), "r"(a[1]), "r"(a[2]), "r"(a[3]), "r"(b[0]), "r"(b[1]));
}
static __device__ __forceinline__ void cpasync16(uint32_t s, const void* g) {
    asm volatile("cp.async.cg.shared.global [%0], [%1], 16;" :: "r"(s), "l"(g));
}
static __device__ __forceinline__ void cp_commit() {
    asm volatile("cp.async.commit_group;" ::: "memory");
}
static __device__ __forceinline__ void cp_wait0() {
    asm volatile("cp.async.wait_group 0;" ::: "memory");
}

// smem layout (bytes):
//  A buf0: [0, 69632)      (reused first as the fp32 staging window [0,69120))
//  A buf1: [69632, 139264)
//  xT_hi : [139264, +36448)   rows c, 136 bf16/row (272B stride)
//  xT_lo : [175712, +36448)
constexpr uint32_t ABUF_SZ = 69632u;
constexpr uint32_t AHALF   = 34816u;
constexpr uint32_t XT_HI   = 139264u;
constexpr uint32_t XT_LO   = XT_HI + 36448u;
constexpr uint32_t SMEM_SZ = XT_LO + 36448u;   // 212160
constexpr int WSTR = 135;

// ---- prep: weight-norm conv weight -> bf16 hi/lo [k][co][ci] ----
__global__ void wn_prep_kernel(const float* __restrict__ conv_v,
                               const float* __restrict__ conv_g) {
    __shared__ float sc[Cn];
    int co = threadIdx.x;
    float s = 0.f;
    for (int i = 0; i < Cn * 3; ++i) {
        float t = conv_v[co * (Cn * 3) + i];
        s += t * t;
    }
    sc[co] = conv_g[co] / sqrtf(s);
    __syncthreads();
    for (int i = threadIdx.x; i < 3 * Cn * Cn; i += Cn) {
        int k = i >> 14, rest = i & 16383, c2 = rest >> 7, ci = rest & 127;
        float v = conv_v[(c2 * Cn + ci) * 3 + k] * sc[c2];
        __nv_bfloat16 h = __float2bfloat16(v);
        gA2_hi[i] = h;
        gA2_lo[i] = __float2bfloat16(v - __bfloat162float(h));
    }
}

// ---- transpose W[b][ci][co][k][l] -> gA_{hi,lo}[b][l][k][co][ci] ----
// 64(ci) x 32(l) tiles, 512 threads: 128B-coalesced reads AND writes.
__global__ __launch_bounds__(512)
void transpose_w_kernel(const float* __restrict__ W) {
    __shared__ float tile[64][33];
    int z = blockIdx.z;
    int k = z % 3, co = (z / 3) & 127, b = z / (3 * Cn);
    int l0 = blockIdx.x * 32, ci0 = blockIdx.y * 64;
    const int tid = threadIdx.x;
    #pragma unroll
    for (int j = 0; j < 4; ++j) {
        int i = tid + j * 512;
        int cir = i >> 5, lc = i & 31;
        tile[cir][lc] =
            W[((((size_t)b * Cn + ci0 + cir) * Cn + co) * 3 + k) * Ln + l0 + lc];
    }
    __syncthreads();
    #pragma unroll
    for (int j = 0; j < 4; ++j) {
        int i = tid + j * 512;
        int lr = i >> 6, cic = i & 63;
        float v = tile[cic][lr];
        __nv_bfloat16 h = __float2bfloat16(v);
        size_t o = ((((size_t)b * Ln + l0 + lr) * 3 + k) * Cn + co) * Cn + ci0 + cic;
        gA_hi[o] = h;
        gA_lo[o] = __float2bfloat16(v - __bfloat162float(h));
    }
}

// ---- main GEMM kernel: HMMA bf16 hi/lo 3-pass, 16 warps, cp.async prefetch ----
template <int PAD, int SHIFT, bool LVC>
__global__ __launch_bounds__(512, 1)
void gemm_hmma_kernel(const float* __restrict__ src,
                      const __nv_bfloat16* __restrict__ Ah,
                      const __nv_bfloat16* __restrict__ Al,
                      const float* __restrict__ biasp,
                      float* __restrict__ dst) {
    constexpr int CROWS = 128 + 2 * PAD;
    extern __shared__ char sm[];
    const uint32_t smb = smem_u32(sm);
    const int tid = threadIdx.x;
    const int b = blockIdx.x >> 8, tile = blockIdx.x & 255;

    // 1) stage fp32 window coalesced into [0, 69120)
    {
        float* ws = (float*)sm;
        const int tb = tile * 128 - PAD;
        const float* xb = src + (size_t)b * Cn * Tn;
        for (int i = tid; i < Cn * CROWS; i += 512) {
            int ci = i / CROWS, c = i - ci * CROWS;
            int t = tb + c;
            ws[ci * WSTR + c] = (t >= 0 && t < Tn) ? xb[(size_t)ci * Tn + t] : 0.f;
        }
    }
    __syncthreads();

    const size_t a_off = LVC ? (size_t)(b * Ln + tile) * 3 * 16384 : 0;
    auto stageA = [&](int k, uint32_t buf) {
        const uint4* sH = (const uint4*)(Ah + a_off + (size_t)k * 16384);
        const uint4* sL = (const uint4*)(Al + a_off + (size_t)k * 16384);
        #pragma unroll
        for (int j = 0; j < 4; ++j) {
            int i = tid + j * 512;
            int co = i >> 4, c8 = (i & 15) << 3;
            uint32_t d = smb + buf + (uint32_t)co * 272u + (uint32_t)c8 * 2u;
            cpasync16(d, sH + i);
            cpasync16(d + AHALF, sL + i);
        }
        cp_commit();
    };

    // 2) prefetch A(k=0) into buf1 (does NOT overlap the live fp32 window)
    stageA(0, ABUF_SZ);

    // 3) transpose window -> xT hi/lo
    {
        const float* ws = (const float*)sm;
        __nv_bfloat16* xh = (__nv_bfloat16*)(sm + XT_HI);
        __nv_bfloat16* xl = (__nv_bfloat16*)(sm + XT_LO);
        for (int i = tid; i < Cn * CROWS; i += 512) {
            int c = i >> 7, ci = i & 127;
            float v = ws[ci * WSTR + c];
            __nv_bfloat16 h = __float2bfloat16(v);
            xh[c * 136 + ci] = h;
            xl[c * 136 + ci] = __float2bfloat16(v - __bfloat162float(h));
        }
    }
    cp_wait0();
    __syncthreads();

    // warp tiling: 16 warps -> 4(co) x 4(s), each 32x32
    const int warp = tid >> 5, lane = tid & 31;
    const int co0 = (warp >> 2) * 32, s0 = (warp & 3) * 32;
    const uint32_t lrow = lane & 15, lcol = (uint32_t)(lane >> 4) << 4;

    float acc[2][4][4];
    #pragma unroll
    for (int mi = 0; mi < 2; ++mi)
        #pragma unroll
        for (int ni = 0; ni < 4; ++ni)
            #pragma unroll
            for (int q = 0; q < 4; ++q) acc[mi][ni][q] = 0.f;

    uint32_t aoffs[2], boffs[2];
    #pragma unroll
    for (int mi = 0; mi < 2; ++mi)
        aoffs[mi] = (uint32_t)(co0 + mi * 16 + lrow) * 272u + lcol;
    #pragma unroll
    for (int p = 0; p < 2; ++p)
        boffs[p] = (uint32_t)(s0 + p * 16 + lrow) * 272u + lcol;

    #pragma unroll
    for (int k = 0; k < 3; ++k) {
        // buffers: k=0 -> buf1, k=1 -> buf0, k=2 -> buf1
        const uint32_t abase = smb + ((k & 1) ? 0u : ABUF_SZ);
        if (k < 2) stageA(k + 1, (k & 1) ? ABUF_SZ : 0u);

        const uint32_t bshift = (uint32_t)(SHIFT * k) * 272u;
        const uint32_t bh_base = smb + XT_HI + bshift;
        const uint32_t bl_base = smb + XT_LO + bshift;

        #pragma unroll 2
        for (int ch = 0; ch < 8; ++ch) {
            const uint32_t cb = (uint32_t)ch * 32u;
            uint32_t ahf[2][4], alf[2][4];
            #pragma unroll
            for (int mi = 0; mi < 2; ++mi) {
                ldm_x4(ahf[mi][0], ahf[mi][1], ahf[mi][2], ahf[mi][3], abase + aoffs[mi] + cb);
                ldm_x4(alf[mi][0], alf[mi][1], alf[mi][2], alf[mi][3], abase + AHALF + aoffs[mi] + cb);
            }
            uint32_t bh[4][2], bl[4][2];
            #pragma unroll
            for (int p = 0; p < 2; ++p) {
                uint32_t r0, r1, r2, r3;
                ldm_x4(r0, r1, r2, r3, bh_base + boffs[p] + cb);
                bh[2 * p][0] = r0; bh[2 * p][1] = r2;
                bh[2 * p + 1][0] = r1; bh[2 * p + 1][1] = r3;
                ldm_x4(r0, r1, r2, r3, bl_base + boffs[p] + cb);
                bl[2 * p][0] = r0; bl[2 * p][1] = r2;
                bl[2 * p + 1][0] = r1; bl[2 * p + 1][1] = r3;
            }
            // pass-major: 8 independent MMAs per pass -> dep distance 8
            #pragma unroll
            for (int mi = 0; mi < 2; ++mi)
                #pragma unroll
                for (int ni = 0; ni < 4; ++ni)
                    mma16816(acc[mi][ni], ahf[mi], bh[ni]);
            #pragma unroll
            for (int mi = 0; mi < 2; ++mi)
                #pragma unroll
                for (int ni = 0; ni < 4; ++ni)
                    mma16816(acc[mi][ni], ahf[mi], bl[ni]);
            #pragma unroll
            for (int mi = 0; mi < 2; ++mi)
                #pragma unroll
                for (int ni = 0; ni < 4; ++ni)
                    mma16816(acc[mi][ni], alf[mi], bh[ni]);
        }
        if (k < 2) {
            cp_wait0();
            __syncthreads();
        }
    }

    // epilogue: bias + leaky, direct float2 stores
    const int g = lane >> 2, q = lane & 3;
    float bv[2][2];
    #pragma unroll
    for (int mi = 0; mi < 2; ++mi)
        #pragma unroll
        for (int h = 0; h < 2; ++h) {
            int co = co0 + mi * 16 + g + h * 8;
            bv[mi][h] = LVC ? biasp[((size_t)b * Cn + co) * Ln + tile] : biasp[co];
        }
    float* dbase = dst + (size_t)b * Cn * Tn + (size_t)tile * 128;
    #pragma unroll
    for (int mi = 0; mi < 2; ++mi)
        #pragma unroll
        for (int ni = 0; ni < 4; ++ni)
            #pragma unroll
            for (int h = 0; h < 2; ++h) {
                int co = co0 + mi * 16 + g + h * 8;
                int s = s0 + ni * 8 + q * 2;
                float v0 = acc[mi][ni][2 * h]     + bv[mi][h];
                float v1 = acc[mi][ni][2 * h + 1] + bv[mi][h];
                v0 = fmaxf(v0, SLOPE * v0);
                v1 = fmaxf(v1, SLOPE * v1);
                *(float2*)(dbase + (size_t)co * Tn + s) = make_float2(v0, v1);
            }
}

// ---- launch ----
extern "C" void kernel_launch(void* const* d_in, const int* in_sizes, int n_in,
                              void* d_out, int out_size) {
    const float* x      = (const float*)d_in[0];
    const float* weight = (const float*)d_in[1];
    const float* bias   = (const float*)d_in[2];
    const float* conv_v = (const float*)d_in[3];
    const float* conv_g = (const float*)d_in[4];
    const float* conv_b = (const float*)d_in[5];
    float* out = (float*)d_out;

    float* gh_ptr;
    cudaGetSymbolAddress((void**)&gh_ptr, g_h);
    __nv_bfloat16 *pAh, *pAl, *pA2h, *pA2l;
    cudaGetSymbolAddress((void**)&pAh, gA_hi);
    cudaGetSymbolAddress((void**)&pAl, gA_lo);
    cudaGetSymbolAddress((void**)&pA2h, gA2_hi);
    cudaGetSymbolAddress((void**)&pA2l, gA2_lo);

    cudaFuncSetAttribute(gemm_hmma_kernel<1, 1, true>,
                         cudaFuncAttributeMaxDynamicSharedMemorySize, SMEM_SZ);
    cudaFuncSetAttribute(gemm_hmma_kernel<3, 3, false>,
                         cudaFuncAttributeMaxDynamicSharedMemorySize, SMEM_SZ);

    wn_prep_kernel<<<1, Cn>>>(conv_v, conv_g);
    transpose_w_kernel<<<dim3(Ln / 32, Cn / 64, Bn * Cn * 3), dim3(512)>>>(weight);
    gemm_hmma_kernel<1, 1, true><<<Bn * Ln, 512, SMEM_SZ>>>(x, pAh, pAl, bias, gh_ptr);
    gemm_hmma_kernel<3, 3, false><<<Bn * Ln, 512, SMEM_SZ>>>(gh_ptr, pA2h, pA2l, conv_b, out);
}

// round 5
// speedup vs baseline: 1.5822x; 1.3337x over previous
#include <cuda_runtime.h>
#include <cuda_bf16.h>
#include <cstdint>

constexpr int Bn = 8, Cn = 128, Tn = 32768, Ln = 256;
constexpr float SLOPE = 0.2f;

// ---- device scratch ----
__device__ __nv_bfloat16 gA_hi[(size_t)Bn * Ln * 3 * Cn * Cn];  // [b][l][k][co][ci]
__device__ __nv_bfloat16 gA_lo[(size_t)Bn * Ln * 3 * Cn * Cn];
__device__ float         g_h  [(size_t)Bn * Cn * Tn];
__device__ __nv_bfloat16 gA2_hi[3 * Cn * Cn];                   // [k][co][ci]
__device__ __nv_bfloat16 gA2_lo[3 * Cn * Cn];

// ---- helpers ----
static __device__ __forceinline__ uint32_t smem_u32(const void* p) {
    uint32_t a;
    asm("{ .reg .u64 t; cvta.to.shared.u64 t, %1; cvt.u32.u64 %0, t; }" : "=r"(a) : "l"(p));
    return a;
}
static __device__ __forceinline__ void ldm_x4(uint32_t &r0, uint32_t &r1,
                                              uint32_t &r2, uint32_t &r3, uint32_t addr) {
    asm volatile("ldmatrix.sync.aligned.m8n8.x4.shared.b16 {%0,%1,%2,%3}, [%4];"
                 : "=r"(r0), "=r"(r1), "=r"(r2), "=r"(r3) : "r"(addr));
}
static __device__ __forceinline__ void mma16816(float* c, const uint32_t* a, const uint32_t* b) {
    asm volatile("mma.sync.aligned.m16n8k16.row.col.f32.bf16.bf16.f32 "
                 "{%0,%1,%2,%3}, {%4,%5,%6,%7}, {%8,%9}, {%0,%1,%2,%3};"
                 : "+f"(c[0]), "+f"(c[1]), "+f"(c[2]), "+f"(c[3])
                 : "r"(a[0]), "r"(a[1]), "r"(a[2]), "r"(a[3]), "r"(b[0]), "r"(b[1]));
}
static __device__ __forceinline__ void cpasync16(uint32_t s, const void* g) {
    asm volatile("cp.async.cg.shared.global [%0], [%1], 16;" :: "r"(s), "l"(g));
}
static __device__ __forceinline__ void cp_commit() {
    asm volatile("cp.async.commit_group;" ::: "memory");
}
static __device__ __forceinline__ void cp_wait0() {
    asm volatile("cp.async.wait_group 0;" ::: "memory");
}

// smem layout (bytes):
//  A buf0: [0, 69632)      (reused first as the fp32 staging window [0,69120))
//  A buf1: [69632, 139264)
//  xT_hi : [139264, +36448)   rows c, 136 bf16/row (272B stride)
//  xT_lo : [175712, +36448)
constexpr uint32_t ABUF_SZ = 69632u;
constexpr uint32_t AHALF   = 34816u;
constexpr uint32_t XT_HI   = 139264u;
constexpr uint32_t XT_LO   = XT_HI + 36448u;
constexpr uint32_t SMEM_SZ = XT_LO + 36448u;   // 212160
constexpr int WSTR = 135;
constexpr int NT = 1024;

// ---- prep: weight-norm conv weight -> bf16 hi/lo [k][co][ci] ----
__global__ void wn_prep_kernel(const float* __restrict__ conv_v,
                               const float* __restrict__ conv_g) {
    __shared__ float sc[Cn];
    int co = threadIdx.x;
    float s = 0.f;
    for (int i = 0; i < Cn * 3; ++i) {
        float t = conv_v[co * (Cn * 3) + i];
        s += t * t;
    }
    sc[co] = conv_g[co] / sqrtf(s);
    __syncthreads();
    for (int i = threadIdx.x; i < 3 * Cn * Cn; i += Cn) {
        int k = i >> 14, rest = i & 16383, c2 = rest >> 7, ci = rest & 127;
        float v = conv_v[(c2 * Cn + ci) * 3 + k] * sc[c2];
        __nv_bfloat16 h = __float2bfloat16(v);
        gA2_hi[i] = h;
        gA2_lo[i] = __float2bfloat16(v - __bfloat162float(h));
    }
}

// ---- transpose W[b][ci][co][k][l] -> gA_{hi,lo}[b][l][k][co][ci] ----
__global__ __launch_bounds__(512)
void transpose_w_kernel(const float* __restrict__ W) {
    __shared__ float tile[64][33];
    int z = blockIdx.z;
    int k = z % 3, co = (z / 3) & 127, b = z / (3 * Cn);
    int l0 = blockIdx.x * 32, ci0 = blockIdx.y * 64;
    const int tid = threadIdx.x;
    #pragma unroll
    for (int j = 0; j < 4; ++j) {
        int i = tid + j * 512;
        int cir = i >> 5, lc = i & 31;
        tile[cir][lc] =
            W[((((size_t)b * Cn + ci0 + cir) * Cn + co) * 3 + k) * Ln + l0 + lc];
    }
    __syncthreads();
    #pragma unroll
    for (int j = 0; j < 4; ++j) {
        int i = tid + j * 512;
        int lr = i >> 6, cic = i & 63;
        float v = tile[cic][lr];
        __nv_bfloat16 h = __float2bfloat16(v);
        size_t o = ((((size_t)b * Ln + l0 + lr) * 3 + k) * Cn + co) * Cn + ci0 + cic;
        gA_hi[o] = h;
        gA_lo[o] = __float2bfloat16(v - __bfloat162float(h));
    }
}

// ---- main GEMM: HMMA bf16 hi/lo 3-pass, 32 warps, warp tile 32x16 ----
template <int PAD, int SHIFT, bool LVC>
__global__ __launch_bounds__(NT, 1)
void gemm_hmma_kernel(const float* __restrict__ src,
                      const __nv_bfloat16* __restrict__ Ah,
                      const __nv_bfloat16* __restrict__ Al,
                      const float* __restrict__ biasp,
                      float* __restrict__ dst) {
    constexpr int CROWS = 128 + 2 * PAD;
    extern __shared__ char sm[];
    const uint32_t smb = smem_u32(sm);
    const int tid = threadIdx.x;
    const int b = blockIdx.x >> 8, tile = blockIdx.x & 255;

    // 1) stage fp32 window coalesced into [0, 69120)
    {
        float* ws = (float*)sm;
        const int tb = tile * 128 - PAD;
        const float* xb = src + (size_t)b * Cn * Tn;
        for (int i = tid; i < Cn * CROWS; i += NT) {
            int ci = i / CROWS, c = i - ci * CROWS;
            int t = tb + c;
            ws[ci * WSTR + c] = (t >= 0 && t < Tn) ? xb[(size_t)ci * Tn + t] : 0.f;
        }
    }
    __syncthreads();

    const size_t a_off = LVC ? (size_t)(b * Ln + tile) * 3 * 16384 : 0;
    auto stageA = [&](int k, uint32_t buf) {
        const uint4* sH = (const uint4*)(Ah + a_off + (size_t)k * 16384);
        const uint4* sL = (const uint4*)(Al + a_off + (size_t)k * 16384);
        #pragma unroll
        for (int j = 0; j < 2; ++j) {
            int i = tid + j * NT;
            int co = i >> 4, c8 = (i & 15) << 3;
            uint32_t d = smb + buf + (uint32_t)co * 272u + (uint32_t)c8 * 2u;
            cpasync16(d, sH + i);
            cpasync16(d + AHALF, sL + i);
        }
        cp_commit();
    };

    // 2) prefetch A(k=0) into buf1 (does NOT overlap the live fp32 window)
    stageA(0, ABUF_SZ);

    // 3) transpose window -> xT hi/lo
    {
        const float* ws = (const float*)sm;
        __nv_bfloat16* xh = (__nv_bfloat16*)(sm + XT_HI);
        __nv_bfloat16* xl = (__nv_bfloat16*)(sm + XT_LO);
        for (int i = tid; i < Cn * CROWS; i += NT) {
            int c = i >> 7, ci = i & 127;
            float v = ws[ci * WSTR + c];
            __nv_bfloat16 h = __float2bfloat16(v);
            xh[c * 136 + ci] = h;
            xl[c * 136 + ci] = __float2bfloat16(v - __bfloat162float(h));
        }
    }
    cp_wait0();
    __syncthreads();

    // warp tiling: 32 warps -> 4(co groups of 32) x 8(s groups of 16)
    const int warp = tid >> 5, lane = tid & 31;
    const int co0 = (warp >> 3) * 32, s0 = (warp & 7) * 16;
    const uint32_t lrow = lane & 15, lcol = (uint32_t)(lane >> 4) << 4;

    float acc[2][2][4];
    #pragma unroll
    for (int mi = 0; mi < 2; ++mi)
        #pragma unroll
        for (int ni = 0; ni < 2; ++ni)
            #pragma unroll
            for (int q = 0; q < 4; ++q) acc[mi][ni][q] = 0.f;

    uint32_t aoffs[2];
    #pragma unroll
    for (int mi = 0; mi < 2; ++mi)
        aoffs[mi] = (uint32_t)(co0 + mi * 16 + lrow) * 272u + lcol;
    const uint32_t boff = (uint32_t)(s0 + lrow) * 272u + lcol;

    #pragma unroll
    for (int k = 0; k < 3; ++k) {
        // buffers: k=0 -> buf1, k=1 -> buf0, k=2 -> buf1
        const uint32_t abase = smb + ((k & 1) ? 0u : ABUF_SZ);
        if (k < 2) stageA(k + 1, (k & 1) ? ABUF_SZ : 0u);

        const uint32_t bshift = (uint32_t)(SHIFT * k) * 272u;
        const uint32_t bh_base = smb + XT_HI + bshift + boff;
        const uint32_t bl_base = smb + XT_LO + bshift + boff;

        #pragma unroll
        for (int ch = 0; ch < 8; ++ch) {
            const uint32_t cb = (uint32_t)ch * 32u;
            uint32_t ahf[2][4], alf[2][4];
            #pragma unroll
            for (int mi = 0; mi < 2; ++mi) {
                ldm_x4(ahf[mi][0], ahf[mi][1], ahf[mi][2], ahf[mi][3], abase + aoffs[mi] + cb);
                ldm_x4(alf[mi][0], alf[mi][1], alf[mi][2], alf[mi][3], abase + AHALF + aoffs[mi] + cb);
            }
            {   // B hi frags -> passes hi*hi and lo*hi (8 independent-ish MMAs)
                uint32_t r0, r1, r2, r3;
                ldm_x4(r0, r1, r2, r3, bh_base + cb);
                uint32_t bh[2][2] = {{r0, r2}, {r1, r3}};
                #pragma unroll
                for (int mi = 0; mi < 2; ++mi)
                    #pragma unroll
                    for (int ni = 0; ni < 2; ++ni)
                        mma16816(acc[mi][ni], ahf[mi], bh[ni]);
                #pragma unroll
                for (int mi = 0; mi < 2; ++mi)
                    #pragma unroll
                    for (int ni = 0; ni < 2; ++ni)
                        mma16816(acc[mi][ni], alf[mi], bh[ni]);
            }
            {   // B lo frags -> pass hi*lo
                uint32_t r0, r1, r2, r3;
                ldm_x4(r0, r1, r2, r3, bl_base + cb);
                uint32_t bl[2][2] = {{r0, r2}, {r1, r3}};
                #pragma unroll
                for (int mi = 0; mi < 2; ++mi)
                    #pragma unroll
                    for (int ni = 0; ni < 2; ++ni)
                        mma16816(acc[mi][ni], ahf[mi], bl[ni]);
            }
        }
        if (k < 2) {
            cp_wait0();
            __syncthreads();
        }
    }

    // epilogue: bias + leaky, direct float2 stores
    const int g = lane >> 2, q = lane & 3;
    float bv[2][2];
    #pragma unroll
    for (int mi = 0; mi < 2; ++mi)
        #pragma unroll
        for (int h = 0; h < 2; ++h) {
            int co = co0 + mi * 16 + g + h * 8;
            bv[mi][h] = LVC ? biasp[((size_t)b * Cn + co) * Ln + tile] : biasp[co];
        }
    float* dbase = dst + (size_t)b * Cn * Tn + (size_t)tile * 128;
    #pragma unroll
    for (int mi = 0; mi < 2; ++mi)
        #pragma unroll
        for (int ni = 0; ni < 2; ++ni)
            #pragma unroll
            for (int h = 0; h < 2; ++h) {
                int co = co0 + mi * 16 + g + h * 8;
                int s = s0 + ni * 8 + q * 2;
                float v0 = acc[mi][ni][2 * h]     + bv[mi][h];
                float v1 = acc[mi][ni][2 * h + 1] + bv[mi][h];
                v0 = fmaxf(v0, SLOPE * v0);
                v1 = fmaxf(v1, SLOPE * v1);
                *(float2*)(dbase + (size_t)co * Tn + s) = make_float2(v0, v1);
            }
}

// ---- launch ----
extern "C" void kernel_launch(void* const* d_in, const int* in_sizes, int n_in,
                              void* d_out, int out_size) {
    const float* x      = (const float*)d_in[0];
    const float* weight = (const float*)d_in[1];
    const float* bias   = (const float*)d_in[2];
    const float* conv_v = (const float*)d_in[3];
    const float* conv_g = (const float*)d_in[4];
    const float* conv_b = (const float*)d_in[5];
    float* out = (float*)d_out;

    float* gh_ptr;
    cudaGetSymbolAddress((void**)&gh_ptr, g_h);
    __nv_bfloat16 *pAh, *pAl, *pA2h, *pA2l;
    cudaGetSymbolAddress((void**)&pAh, gA_hi);
    cudaGetSymbolAddress((void**)&pAl, gA_lo);
    cudaGetSymbolAddress((void**)&pA2h, gA2_hi);
    cudaGetSymbolAddress((void**)&pA2l, gA2_lo);

    cudaFuncSetAttribute(gemm_hmma_kernel<1, 1, true>,
                         cudaFuncAttributeMaxDynamicSharedMemorySize, SMEM_SZ);
    cudaFuncSetAttribute(gemm_hmma_kernel<3, 3, false>,
                         cudaFuncAttributeMaxDynamicSharedMemorySize, SMEM_SZ);

    wn_prep_kernel<<<1, Cn>>>(conv_v, conv_g);
    transpose_w_kernel<<<dim3(Ln / 32, Cn / 64, Bn * Cn * 3), dim3(512)>>>(weight);
    gemm_hmma_kernel<1, 1, true><<<Bn * Ln, NT, SMEM_SZ>>>(x, pAh, pAl, bias, gh_ptr);
    gemm_hmma_kernel<3, 3, false><<<Bn * Ln, NT, SMEM_SZ>>>(gh_ptr, pA2h, pA2l, conv_b, out);
}

// round 6
// speedup vs baseline: 1.8087x; 1.1432x over previous
#include <cuda_runtime.h>
#include <cuda_fp16.h>
#include <cstdint>

constexpr int Bn = 8, Cn = 128, Tn = 32768, Ln = 256;
constexpr float SLOPE = 0.2f;

// ---- device scratch ----
__device__ __half gA_hi[(size_t)Bn * Ln * 3 * Cn * Cn];  // [b][l][k][co][ci] fp16 (single)
__device__ float  g_h  [(size_t)Bn * Cn * Tn];
__device__ __half gA2_hi[3 * Cn * Cn];                   // dconv w hi [k][co][ci]
__device__ __half gA2_lo[3 * Cn * Cn];                   // dconv w lo

// ---- helpers ----
static __device__ __forceinline__ uint32_t smem_u32(const void* p) {
    uint32_t a;
    asm("{ .reg .u64 t; cvta.to.shared.u64 t, %1; cvt.u32.u64 %0, t; }" : "=r"(a) : "l"(p));
    return a;
}
static __device__ __forceinline__ void ldm_x4(uint32_t &r0, uint32_t &r1,
                                              uint32_t &r2, uint32_t &r3, uint32_t addr) {
    asm volatile("ldmatrix.sync.aligned.m8n8.x4.shared.b16 {%0,%1,%2,%3}, [%4];"
                 : "=r"(r0), "=r"(r1), "=r"(r2), "=r"(r3) : "r"(addr));
}
static __device__ __forceinline__ void mma16816(float* c, const uint32_t* a, const uint32_t* b) {
    asm volatile("mma.sync.aligned.m16n8k16.row.col.f32.f16.f16.f32 "
                 "{%0,%1,%2,%3}, {%4,%5,%6,%7}, {%8,%9}, {%0,%1,%2,%3};"
                 : "+f"(c[0]), "+f"(c[1]), "+f"(c[2]), "+f"(c[3])
                 : "r"(a[0]), "r"(a[1]), "r"(a[2]), "r"(a[3]), "r"(b[0]), "r"(b[1]));
}
static __device__ __forceinline__ void cpasync16(uint32_t s, const void* g) {
    asm volatile("cp.async.cg.shared.global [%0], [%1], 16;" :: "r"(s), "l"(g));
}
static __device__ __forceinline__ void cp_commit() {
    asm volatile("cp.async.commit_group;" ::: "memory");
}
static __device__ __forceinline__ void cp_wait0() {
    asm volatile("cp.async.wait_group 0;" ::: "memory");
}

constexpr uint32_t AHALF  = 34816u;   // one A tile (128 rows x 272B)
constexpr uint32_t BUF_E  = 69632u;   // even-k A buffer (beyond fp32 window 69120)
constexpr int WSTR = 135;
constexpr int NT = 1024;

// ---- prep: weight-norm conv weight -> fp16 hi/lo [k][co][ci] ----
__global__ void wn_prep_kernel(const float* __restrict__ conv_v,
                               const float* __restrict__ conv_g) {
    __shared__ float sc[Cn];
    int co = threadIdx.x;
    float s = 0.f;
    for (int i = 0; i < Cn * 3; ++i) {
        float t = conv_v[co * (Cn * 3) + i];
        s += t * t;
    }
    sc[co] = conv_g[co] / sqrtf(s);
    __syncthreads();
    for (int i = threadIdx.x; i < 3 * Cn * Cn; i += Cn) {
        int k = i >> 14, rest = i & 16383, c2 = rest >> 7, ci = rest & 127;
        float v = conv_v[(c2 * Cn + ci) * 3 + k] * sc[c2];
        __half h = __float2half_rn(v);
        gA2_hi[i] = h;
        gA2_lo[i] = __float2half_rn(v - __half2float(h));
    }
}

// ---- transpose W[b][ci][co][k][l] -> gA_hi[b][l][k][co][ci] fp16 ----
__global__ __launch_bounds__(512)
void transpose_w_kernel(const float* __restrict__ W) {
    __shared__ float tile[64][33];
    int z = blockIdx.z;
    int k = z % 3, co = (z / 3) & 127, b = z / (3 * Cn);
    int l0 = blockIdx.x * 32, ci0 = blockIdx.y * 64;
    const int tid = threadIdx.x;
    #pragma unroll
    for (int j = 0; j < 4; ++j) {
        int i = tid + j * 512;
        int cir = i >> 5, lc = i & 31;
        tile[cir][lc] =
            W[((((size_t)b * Cn + ci0 + cir) * Cn + co) * 3 + k) * Ln + l0 + lc];
    }
    __syncthreads();
    #pragma unroll
    for (int j = 0; j < 4; ++j) {
        int i = tid + j * 512;
        int lr = i >> 6, cic = i & 63;
        size_t o = ((((size_t)b * Ln + l0 + lr) * 3 + k) * Cn + co) * Cn + ci0 + cic;
        gA_hi[o] = __float2half_rn(tile[cic][lr]);
    }
}

// ---- main GEMM: HMMA fp16, PASSES = 2 (A single) or 3 (A hi/lo) ----
// smem: fp32 window [0, 69120) overlaps BUF_ODD(0); BUF_EVEN at 69632.
// xT_hi/xT_lo after the A buffers; rows c, 136 fp16/row (272B stride).
template <int PAD, int SHIFT, bool LVC, int PASSES>
__global__ __launch_bounds__(NT, 1)
void gemm_hmma_kernel(const float* __restrict__ src,
                      const __half* __restrict__ Ah,
                      const __half* __restrict__ Al,
                      const float* __restrict__ biasp,
                      float* __restrict__ dst) {
    constexpr int CROWS = 128 + 2 * PAD;
    constexpr uint32_t ABYTES = (PASSES == 3) ? 2u * AHALF : AHALF;
    constexpr uint32_t XT_HI = BUF_E + ABYTES;
    constexpr uint32_t XT_LO = XT_HI + 36448u;
    extern __shared__ char sm[];
    const uint32_t smb = smem_u32(sm);
    const int tid = threadIdx.x;
    const int b = blockIdx.x >> 8, tile = blockIdx.x & 255;

    // 1) stage fp32 window coalesced into [0, 69120)
    {
        float* ws = (float*)sm;
        const int tb = tile * 128 - PAD;
        const float* xb = src + (size_t)b * Cn * Tn;
        for (int i = tid; i < Cn * CROWS; i += NT) {
            int ci = i / CROWS, c = i - ci * CROWS;
            int t = tb + c;
            ws[ci * WSTR + c] = (t >= 0 && t < Tn) ? xb[(size_t)ci * Tn + t] : 0.f;
        }
    }
    __syncthreads();

    const size_t a_off = LVC ? (size_t)(b * Ln + tile) * 3 * 16384 : 0;
    auto stageA = [&](int k, uint32_t buf) {
        const uint4* sH = (const uint4*)(Ah + a_off + (size_t)k * 16384);
        const uint4* sL = (const uint4*)(Al + a_off + (size_t)k * 16384);
        #pragma unroll
        for (int j = 0; j < 2; ++j) {
            int i = tid + j * NT;
            int co = i >> 4, c8 = (i & 15) << 3;
            uint32_t d = smb + buf + (uint32_t)co * 272u + (uint32_t)c8 * 2u;
            cpasync16(d, sH + i);
            if (PASSES == 3) cpasync16(d + AHALF, sL + i);
        }
        cp_commit();
    };

    // 2) prefetch A(k=0) into even buffer (beyond the live fp32 window)
    stageA(0, BUF_E);

    // 3) transpose window -> xT hi/lo (fp16 split of x)
    {
        const float* ws = (const float*)sm;
        __half* xh = (__half*)(sm + XT_HI);
        __half* xl = (__half*)(sm + XT_LO);
        for (int i = tid; i < Cn * CROWS; i += NT) {
            int c = i >> 7, ci = i & 127;
            float v = ws[ci * WSTR + c];
            __half h = __float2half_rn(v);
            xh[c * 136 + ci] = h;
            xl[c * 136 + ci] = __float2half_rn(v - __half2float(h));
        }
    }
    cp_wait0();
    __syncthreads();

    // warp tiling: 32 warps -> 4(co groups of 32) x 8(s groups of 16)
    const int warp = tid >> 5, lane = tid & 31;
    const int co0 = (warp >> 3) * 32, s0 = (warp & 7) * 16;
    const uint32_t lrow = lane & 15, lcol = (uint32_t)(lane >> 4) << 4;

    float acc[2][2][4];
    #pragma unroll
    for (int mi = 0; mi < 2; ++mi)
        #pragma unroll
        for (int ni = 0; ni < 2; ++ni)
            #pragma unroll
            for (int q = 0; q < 4; ++q) acc[mi][ni][q] = 0.f;

    uint32_t aoffs[2];
    #pragma unroll
    for (int mi = 0; mi < 2; ++mi)
        aoffs[mi] = (uint32_t)(co0 + mi * 16 + lrow) * 272u + lcol;
    const uint32_t boff = (uint32_t)(s0 + lrow) * 272u + lcol;

    #pragma unroll
    for (int k = 0; k < 3; ++k) {
        // buffers: even k -> BUF_E, odd k -> 0
        const uint32_t abase = smb + ((k & 1) ? 0u : BUF_E);
        if (k < 2) stageA(k + 1, (k & 1) ? BUF_E : 0u);

        const uint32_t bshift = (uint32_t)(SHIFT * k) * 272u;
        const uint32_t bh_base = smb + XT_HI + bshift + boff;
        const uint32_t bl_base = smb + XT_LO + bshift + boff;

        #pragma unroll
        for (int ch = 0; ch < 8; ++ch) {
            const uint32_t cb = (uint32_t)ch * 32u;
            uint32_t ahf[2][4];
            #pragma unroll
            for (int mi = 0; mi < 2; ++mi)
                ldm_x4(ahf[mi][0], ahf[mi][1], ahf[mi][2], ahf[mi][3], abase + aoffs[mi] + cb);
            uint32_t alf[2][4];
            if (PASSES == 3) {
                #pragma unroll
                for (int mi = 0; mi < 2; ++mi)
                    ldm_x4(alf[mi][0], alf[mi][1], alf[mi][2], alf[mi][3],
                           abase + AHALF + aoffs[mi] + cb);
            }
            {   // B hi frags: pass wh*xh (+ wl*xh when 3-pass)
                uint32_t r0, r1, r2, r3;
                ldm_x4(r0, r1, r2, r3, bh_base + cb);
                uint32_t bh[2][2] = {{r0, r2}, {r1, r3}};
                #pragma unroll
                for (int mi = 0; mi < 2; ++mi)
                    #pragma unroll
                    for (int ni = 0; ni < 2; ++ni)
                        mma16816(acc[mi][ni], ahf[mi], bh[ni]);
                if (PASSES == 3) {
                    #pragma unroll
                    for (int mi = 0; mi < 2; ++mi)
                        #pragma unroll
                        for (int ni = 0; ni < 2; ++ni)
                            mma16816(acc[mi][ni], alf[mi], bh[ni]);
                }
            }
            {   // B lo frags: pass wh*xl
                uint32_t r0, r1, r2, r3;
                ldm_x4(r0, r1, r2, r3, bl_base + cb);
                uint32_t bl[2][2] = {{r0, r2}, {r1, r3}};
                #pragma unroll
                for (int mi = 0; mi < 2; ++mi)
                    #pragma unroll
                    for (int ni = 0; ni < 2; ++ni)
                        mma16816(acc[mi][ni], ahf[mi], bl[ni]);
            }
        }
        if (k < 2) {
            cp_wait0();
            __syncthreads();
        }
    }

    // epilogue: bias + leaky, direct float2 stores
    const int g = lane >> 2, q = lane & 3;
    float bv[2][2];
    #pragma unroll
    for (int mi = 0; mi < 2; ++mi)
        #pragma unroll
        for (int h = 0; h < 2; ++h) {
            int co = co0 + mi * 16 + g + h * 8;
            bv[mi][h] = LVC ? biasp[((size_t)b * Cn + co) * Ln + tile] : biasp[co];
        }
    float* dbase = dst + (size_t)b * Cn * Tn + (size_t)tile * 128;
    #pragma unroll
    for (int mi = 0; mi < 2; ++mi)
        #pragma unroll
        for (int ni = 0; ni < 2; ++ni)
            #pragma unroll
            for (int h = 0; h < 2; ++h) {
                int co = co0 + mi * 16 + g + h * 8;
                int s = s0 + ni * 8 + q * 2;
                float v0 = acc[mi][ni][2 * h]     + bv[mi][h];
                float v1 = acc[mi][ni][2 * h + 1] + bv[mi][h];
                v0 = fmaxf(v0, SLOPE * v0);
                v1 = fmaxf(v1, SLOPE * v1);
                *(float2*)(dbase + (size_t)co * Tn + s) = make_float2(v0, v1);
            }
}

constexpr uint32_t SMEM_LVC = BUF_E + AHALF + 2u * 36448u;       // 177344
constexpr uint32_t SMEM_DCV = BUF_E + 2u * AHALF + 2u * 36448u;  // 212160

// ---- launch ----
extern "C" void kernel_launch(void* const* d_in, const int* in_sizes, int n_in,
                              void* d_out, int out_size) {
    const float* x      = (const float*)d_in[0];
    const float* weight = (const float*)d_in[1];
    const float* bias   = (const float*)d_in[2];
    const float* conv_v = (const float*)d_in[3];
    const float* conv_g = (const float*)d_in[4];
    const float* conv_b = (const float*)d_in[5];
    float* out = (float*)d_out;

    float* gh_ptr;
    cudaGetSymbolAddress((void**)&gh_ptr, g_h);
    __half *pAh, *pA2h, *pA2l;
    cudaGetSymbolAddress((void**)&pAh, gA_hi);
    cudaGetSymbolAddress((void**)&pA2h, gA2_hi);
    cudaGetSymbolAddress((void**)&pA2l, gA2_lo);

    cudaFuncSetAttribute((const void*)gemm_hmma_kernel<1, 1, true, 2>,
                         cudaFuncAttributeMaxDynamicSharedMemorySize, SMEM_LVC);
    cudaFuncSetAttribute((const void*)gemm_hmma_kernel<3, 3, false, 3>,
                         cudaFuncAttributeMaxDynamicSharedMemorySize, SMEM_DCV);

    wn_prep_kernel<<<1, Cn>>>(conv_v, conv_g);
    transpose_w_kernel<<<dim3(Ln / 32, Cn / 64, Bn * Cn * 3), dim3(512)>>>(weight);
    gemm_hmma_kernel<1, 1, true, 2><<<Bn * Ln, NT, SMEM_LVC>>>(x, pAh, pAh, bias, gh_ptr);
    gemm_hmma_kernel<3, 3, false, 3><<<Bn * Ln, NT, SMEM_DCV>>>(gh_ptr, pA2h, pA2l, conv_b, out);
}

// round 7
// speedup vs baseline: 2.2556x; 1.2470x over previous
#include <cuda_runtime.h>
#include <cuda_fp16.h>
#include <cstdint>

constexpr int Bn = 8, Cn = 128, Tn = 32768, Ln = 256;
constexpr float SLOPE = 0.2f;

// ---- device scratch ----
__device__ __half gA  [(size_t)Bn * Ln * 3 * Cn * Cn];  // lvc weight [b][l][k][co][ci] fp16
__device__ __half g_h [(size_t)Bn * Cn * Tn];           // LVC output, fp16 [b][co][t]
__device__ __half gA2 [3 * Cn * Cn];                    // dconv weight [k][co][ci] fp16

// ---- helpers ----
static __device__ __forceinline__ uint32_t smem_u32(const void* p) {
    uint32_t a;
    asm("{ .reg .u64 t; cvta.to.shared.u64 t, %1; cvt.u32.u64 %0, t; }" : "=r"(a) : "l"(p));
    return a;
}
static __device__ __forceinline__ void ldm_x4(uint32_t &r0, uint32_t &r1,
                                              uint32_t &r2, uint32_t &r3, uint32_t addr) {
    asm volatile("ldmatrix.sync.aligned.m8n8.x4.shared.b16 {%0,%1,%2,%3}, [%4];"
                 : "=r"(r0), "=r"(r1), "=r"(r2), "=r"(r3) : "r"(addr));
}
static __device__ __forceinline__ void mma16816(float* c, const uint32_t* a, const uint32_t* b) {
    asm volatile("mma.sync.aligned.m16n8k16.row.col.f32.f16.f16.f32 "
                 "{%0,%1,%2,%3}, {%4,%5,%6,%7}, {%8,%9}, {%0,%1,%2,%3};"
                 : "+f"(c[0]), "+f"(c[1]), "+f"(c[2]), "+f"(c[3])
                 : "r"(a[0]), "r"(a[1]), "r"(a[2]), "r"(a[3]), "r"(b[0]), "r"(b[1]));
}
static __device__ __forceinline__ void cpasync16(uint32_t s, const void* g) {
    asm volatile("cp.async.cg.shared.global [%0], [%1], 16;" :: "r"(s), "l"(g));
}
static __device__ __forceinline__ void cp_commit() {
    asm volatile("cp.async.commit_group;" ::: "memory");
}
static __device__ __forceinline__ void cp_wait0() {
    asm volatile("cp.async.wait_group 0;" ::: "memory");
}

// smem layout (bytes):
//   fp32 window [0, 69120)   (128 rows x 135 floats)
//   A tiles k=0..2 at ABASE + k*ATILE  (128 rows x 272B each)
//   xT (fp16)   [XH, XH+36448)  rows c, 136 halves/row (272B stride)
constexpr uint32_t ABASE = 69632u;
constexpr uint32_t ATILE = 34816u;
constexpr uint32_t XH    = ABASE + 3u * ATILE;     // 174080
constexpr uint32_t SMEM_SZ = XH + 36448u;          // 210528
constexpr int WSTR = 135;
constexpr int NT = 1024;

// ---- prep: weight-norm conv weight -> fp16 [k][co][ci] ----
__global__ void wn_prep_kernel(const float* __restrict__ conv_v,
                               const float* __restrict__ conv_g) {
    __shared__ float sc[Cn];
    int co = threadIdx.x;
    float s = 0.f;
    for (int i = 0; i < Cn * 3; ++i) {
        float t = conv_v[co * (Cn * 3) + i];
        s += t * t;
    }
    sc[co] = conv_g[co] / sqrtf(s);
    __syncthreads();
    for (int i = threadIdx.x; i < 3 * Cn * Cn; i += Cn) {
        int k = i >> 14, rest = i & 16383, c2 = rest >> 7, ci = rest & 127;
        gA2[i] = __float2half_rn(conv_v[(c2 * Cn + ci) * 3 + k] * sc[c2]);
    }
}

// ---- transpose W[b][ci][co][k][l] -> gA[b][l][k][co][ci] fp16 ----
__global__ __launch_bounds__(512)
void transpose_w_kernel(const float* __restrict__ W) {
    __shared__ float tile[64][33];
    int z = blockIdx.z;
    int k = z % 3, co = (z / 3) & 127, b = z / (3 * Cn);
    int l0 = blockIdx.x * 32, ci0 = blockIdx.y * 64;
    const int tid = threadIdx.x;
    #pragma unroll
    for (int j = 0; j < 4; ++j) {
        int i = tid + j * 512;
        int cir = i >> 5, lc = i & 31;
        tile[cir][lc] =
            W[((((size_t)b * Cn + ci0 + cir) * Cn + co) * 3 + k) * Ln + l0 + lc];
    }
    __syncthreads();
    #pragma unroll
    for (int j = 0; j < 4; ++j) {
        int i = tid + j * 512;
        int lr = i >> 6, cic = i & 63;
        size_t o = ((((size_t)b * Ln + l0 + lr) * 3 + k) * Cn + co) * Cn + ci0 + cic;
        gA[o] = __float2half_rn(tile[cic][lr]);
    }
}

// ---- main GEMM: single-pass fp16 HMMA, all A tiles resident, barrier-free k-loop ----
// SRC16: src is fp16 (dconv reading g_h) vs fp32 (lvc reading x)
// OUT16: dst is fp16 (lvc writing g_h) vs fp32 (dconv writing out)
template <int PAD, int SHIFT, bool LVC, bool SRC16, bool OUT16>
__global__ __launch_bounds__(NT, 1)
void gemm_hmma_kernel(const void* __restrict__ src_v,
                      const __half* __restrict__ Aw,
                      const float* __restrict__ biasp,
                      void* __restrict__ dst_v) {
    constexpr int CROWS = 128 + 2 * PAD;
    extern __shared__ char sm[];
    const uint32_t smb = smem_u32(sm);
    const int tid = threadIdx.x;
    const int b = blockIdx.x >> 8, tile = blockIdx.x & 255;

    // 1) stage window coalesced into fp32 smem [0, 69120)
    {
        float* ws = (float*)sm;
        const int tb = tile * 128 - PAD;
        for (int i = tid; i < Cn * CROWS; i += NT) {
            int ci = i / CROWS, c = i - ci * CROWS;
            int t = tb + c;
            float v = 0.f;
            if (t >= 0 && t < Tn) {
                if (SRC16)
                    v = __half2float(((const __half*)src_v)[(size_t)(b * Cn + ci) * Tn + t]);
                else
                    v = ((const float*)src_v)[(size_t)(b * Cn + ci) * Tn + t];
            }
            ws[ci * WSTR + c] = v;
        }
    }

    // 2) cp.async all three A tiles (region disjoint from window & xT)
    {
        const size_t a_off = LVC ? (size_t)(b * Ln + tile) * 3 * 16384 : 0;
        const uint4* sA = (const uint4*)(Aw + a_off);
        #pragma unroll
        for (int j = 0; j < 6; ++j) {
            int i = tid + j * NT;          // i in [0, 6144): k*2048 + row idx
            int k = i >> 11, r = i & 2047;
            int co = r >> 4, c8 = (r & 15) << 3;
            uint32_t d = smb + ABASE + (uint32_t)k * ATILE
                       + (uint32_t)co * 272u + (uint32_t)c8 * 2u;
            cpasync16(d, sA + i);
        }
        cp_commit();
    }
    __syncthreads();

    // 3) transpose window -> xT fp16 [c][ci]
    {
        const float* ws = (const float*)sm;
        __half* xh = (__half*)(sm + XH);
        for (int i = tid; i < Cn * CROWS; i += NT) {
            int c = i >> 7, ci = i & 127;
            xh[c * 136 + ci] = __float2half_rn(ws[ci * WSTR + c]);
        }
    }
    cp_wait0();
    __syncthreads();

    // warp tiling: 32 warps -> 4(co groups of 32) x 8(s groups of 16)
    const int warp = tid >> 5, lane = tid & 31;
    const int co0 = (warp >> 3) * 32, s0 = (warp & 7) * 16;
    const uint32_t lrow = lane & 15, lcol = (uint32_t)(lane >> 4) << 4;

    float acc[2][2][4];
    #pragma unroll
    for (int mi = 0; mi < 2; ++mi)
        #pragma unroll
        for (int ni = 0; ni < 2; ++ni)
            #pragma unroll
            for (int q = 0; q < 4; ++q) acc[mi][ni][q] = 0.f;

    uint32_t aoffs[2];
    #pragma unroll
    for (int mi = 0; mi < 2; ++mi)
        aoffs[mi] = smb + ABASE + (uint32_t)(co0 + mi * 16 + lrow) * 272u + lcol;
    const uint32_t boff = smb + XH + (uint32_t)(s0 + lrow) * 272u + lcol;

    // 4) barrier-free mainloop: 3 k-chunks x 8 ci-chunks, 3 LDSM + 4 MMA each
    #pragma unroll
    for (int k = 0; k < 3; ++k) {
        const uint32_t ak = (uint32_t)k * ATILE;
        const uint32_t bk = (uint32_t)(SHIFT * k) * 272u;
        #pragma unroll
        for (int ch = 0; ch < 8; ++ch) {
            const uint32_t cb = (uint32_t)ch * 32u;
            uint32_t af[2][4];
            #pragma unroll
            for (int mi = 0; mi < 2; ++mi)
                ldm_x4(af[mi][0], af[mi][1], af[mi][2], af[mi][3], aoffs[mi] + ak + cb);
            uint32_t r0, r1, r2, r3;
            ldm_x4(r0, r1, r2, r3, boff + bk + cb);
            uint32_t bf[2][2] = {{r0, r2}, {r1, r3}};
            #pragma unroll
            for (int mi = 0; mi < 2; ++mi)
                #pragma unroll
                for (int ni = 0; ni < 2; ++ni)
                    mma16816(acc[mi][ni], af[mi], bf[ni]);
        }
    }

    // 5) epilogue: bias + leaky
    const int g = lane >> 2, q = lane & 3;
    float bv[2][2];
    #pragma unroll
    for (int mi = 0; mi < 2; ++mi)
        #pragma unroll
        for (int h = 0; h < 2; ++h) {
            int co = co0 + mi * 16 + g + h * 8;
            bv[mi][h] = LVC ? biasp[((size_t)b * Cn + co) * Ln + tile] : biasp[co];
        }
    #pragma unroll
    for (int mi = 0; mi < 2; ++mi)
        #pragma unroll
        for (int ni = 0; ni < 2; ++ni)
            #pragma unroll
            for (int h = 0; h < 2; ++h) {
                int co = co0 + mi * 16 + g + h * 8;
                int s = s0 + ni * 8 + q * 2;
                float v0 = acc[mi][ni][2 * h]     + bv[mi][h];
                float v1 = acc[mi][ni][2 * h + 1] + bv[mi][h];
                v0 = fmaxf(v0, SLOPE * v0);
                v1 = fmaxf(v1, SLOPE * v1);
                size_t off = (size_t)(b * Cn + co) * Tn + (size_t)tile * 128 + s;
                if (OUT16)
                    *(__half2*)((__half*)dst_v + off) = __floats2half2_rn(v0, v1);
                else
                    *(float2*)((float*)dst_v + off) = make_float2(v0, v1);
            }
}

// ---- launch ----
extern "C" void kernel_launch(void* const* d_in, const int* in_sizes, int n_in,
                              void* d_out, int out_size) {
    const float* x      = (const float*)d_in[0];
    const float* weight = (const float*)d_in[1];
    const float* bias   = (const float*)d_in[2];
    const float* conv_v = (const float*)d_in[3];
    const float* conv_g = (const float*)d_in[4];
    const float* conv_b = (const float*)d_in[5];

    __half *gh_ptr, *pA, *pA2;
    cudaGetSymbolAddress((void**)&gh_ptr, g_h);
    cudaGetSymbolAddress((void**)&pA, gA);
    cudaGetSymbolAddress((void**)&pA2, gA2);

    cudaFuncSetAttribute((const void*)gemm_hmma_kernel<1, 1, true, false, true>,
                         cudaFuncAttributeMaxDynamicSharedMemorySize, SMEM_SZ);
    cudaFuncSetAttribute((const void*)gemm_hmma_kernel<3, 3, false, true, false>,
                         cudaFuncAttributeMaxDynamicSharedMemorySize, SMEM_SZ);

    wn_prep_kernel<<<1, Cn>>>(conv_v, conv_g);
    transpose_w_kernel<<<dim3(Ln / 32, Cn / 64, Bn * Cn * 3), dim3(512)>>>(weight);
    gemm_hmma_kernel<1, 1, true, false, true>
        <<<Bn * Ln, NT, SMEM_SZ>>>(x, pA, bias, gh_ptr);
    gemm_hmma_kernel<3, 3, false, true, false>
        <<<Bn * Ln, NT, SMEM_SZ>>>(gh_ptr, pA2, conv_b, d_out);
}